// round 4
// baseline (speedup 1.0000x reference)
#include <cuda_runtime.h>
#include <math.h>

// Problem constants
#define BB   4
#define HH   1024
#define LL   8192
#define KD   64
#define KLEN 512      // KD * 2^(NS-1)

// Scratch (static device allocations are the allowed mechanism)
__device__ float g_k[HH * KLEN];              // normalized combined kernel, [h][t]
__device__ float g_v[(size_t)BB * HH * LL];   // gelu(conv + u*D), [b][h][l]  (128 MB)

// ---------- f32x2 packed helpers (Blackwell FFMA2) ----------
__device__ __forceinline__ unsigned long long pk2(float a, float b) {
    unsigned long long r;
    asm("mov.b64 %0, {%1, %2};" : "=l"(r) : "f"(a), "f"(b));
    return r;
}
__device__ __forceinline__ void upk2(unsigned long long v, float& a, float& b) {
    asm("mov.b64 {%0, %1}, %2;" : "=f"(a), "=f"(b) : "l"(v));
}
__device__ __forceinline__ void fma2(unsigned long long& d, unsigned long long a,
                                     unsigned long long b) {
    asm("fma.rn.f32x2 %0, %1, %2, %0;" : "+l"(d) : "l"(a), "l"(b));
}

// ============================================================
// Kernel 1: build combined, normalized conv kernel per head.
// Exactly mirrors jnp: coord=(t+0.5)/s-0.5, clip[0,63], floor, lerp,
// scale 2^(3-i), sum over 4 scales, then / L2 norm.
// ============================================================
__global__ void __launch_bounds__(128) build_k_kernel(
    const float* __restrict__ k0, const float* __restrict__ k1,
    const float* __restrict__ k2, const float* __restrict__ k3)
{
    int h   = blockIdx.x;
    int tid = threadIdx.x;
    const float* ks[4] = { k0 + h * KD, k1 + h * KD, k2 + h * KD, k3 + h * KD };

    float vals[4];
    float ss = 0.0f;
#pragma unroll
    for (int r = 0; r < 4; r++) {
        int t = tid + r * 128;           // 0..511
        float acc = 0.0f;
#pragma unroll
        for (int i = 0; i < 4; i++) {
            int len = KD << i;           // 64,128,256,512
            if (t < len) {
                float s = (float)(1 << i);
                float coord = (t + 0.5f) / s - 0.5f;
                coord = fminf(fmaxf(coord, 0.0f), 63.0f);
                int lo  = (int)floorf(coord);
                float w = coord - (float)lo;
                int hi  = min(lo + 1, 63);
                float val = ks[i][lo] * (1.0f - w) + ks[i][hi] * w;
                acc += val * (float)(1 << (3 - i));
            }
        }
        vals[r] = acc;
        ss += acc * acc;
    }

    __shared__ float red[128];
    red[tid] = ss;
    __syncthreads();
    for (int s = 64; s > 0; s >>= 1) {
        if (tid < s) red[tid] += red[tid + s];
        __syncthreads();
    }
    float inv = 1.0f / sqrtf(red[0]);
#pragma unroll
    for (int r = 0; r < 4; r++)
        g_k[h * KLEN + tid + r * 128] = vals[r] * inv;
}

// ============================================================
// Kernel 2: causal 512-tap conv + u*D + exact GELU -> g_v
// Tile: 2048 outputs/block, 256 threads, 8 consecutive outputs/thread.
// Inner loop: 4 taps per chunk, packed f32x2 FMAs (16 FFMA2 / chunk).
// ============================================================
#define CTILE 2048

__global__ void __launch_bounds__(256) conv_gelu_kernel(
    const float* __restrict__ u, const float* __restrict__ D)
{
    int bh  = blockIdx.y;            // b*H + h
    int h   = bh & (HH - 1);
    int l0  = blockIdx.x * CTILE;
    int tid = threadIdx.x;

    __shared__ float k_s[KLEN];
    __shared__ float u_s[KLEN + CTILE];   // 512 halo + 2048

    const float* ub = u + (size_t)bh * LL;

#pragma unroll
    for (int i = 0; i < 2; i++)
        k_s[tid + i * 256] = g_k[h * KLEN + tid + i * 256];
#pragma unroll
    for (int i = 0; i < 10; i++) {
        int idx = tid + i * 256;
        int g = l0 - KLEN + idx;
        u_s[idx] = (g >= 0) ? ub[g] : 0.0f;
    }
    __syncthreads();

    int li = tid * 8;
    const float* up = u_s + KLEN + li;

    unsigned long long acc2[4];
#pragma unroll
    for (int p = 0; p < 4; p++) acc2[p] = 0ull;

#pragma unroll 2
    for (int t = 0; t < KLEN; t += 4) {
        float4 k4 = *reinterpret_cast<const float4*>(k_s + t);
        float uv[12];
        *reinterpret_cast<float4*>(uv)     = *reinterpret_cast<const float4*>(up - t - 4);
        *reinterpret_cast<float4*>(uv + 4) = *reinterpret_cast<const float4*>(up - t);
        *reinterpret_cast<float4*>(uv + 8) = *reinterpret_cast<const float4*>(up - t + 4);
        const unsigned long long* uvl = reinterpret_cast<const unsigned long long*>(uv);

        unsigned long long kp0 = pk2(k4.x, k4.x);
        unsigned long long kp1 = pk2(k4.y, k4.y);
        unsigned long long kp2 = pk2(k4.z, k4.z);
        unsigned long long kp3 = pk2(k4.w, k4.w);
        unsigned long long po[5];
#pragma unroll
        for (int q = 0; q < 5; q++) po[q] = pk2(uv[2 * q + 1], uv[2 * q + 2]);

        // acc pair p covers outputs (2p, 2p+1); tap t+j uses up[2p - t - j] pair
#pragma unroll
        for (int p = 0; p < 4; p++) {
            fma2(acc2[p], kp0, uvl[p + 2]);   // j=0 : even pair
            fma2(acc2[p], kp1, po[p + 1]);    // j=1 : odd  pair
            fma2(acc2[p], kp2, uvl[p + 1]);   // j=2 : even pair
            fma2(acc2[p], kp3, po[p]);        // j=3 : odd  pair
        }
    }

    float res[8];
#pragma unroll
    for (int p = 0; p < 4; p++) upk2(acc2[p], res[2 * p], res[2 * p + 1]);

    float d = D[h];
    float4 uc0 = *reinterpret_cast<const float4*>(up);
    float4 uc1 = *reinterpret_cast<const float4*>(up + 4);
    float uu[8] = { uc0.x, uc0.y, uc0.z, uc0.w, uc1.x, uc1.y, uc1.z, uc1.w };

    float outv[8];
#pragma unroll
    for (int r = 0; r < 8; r++) {
        float x = res[r] + uu[r] * d;
        outv[r] = 0.5f * x * (1.0f + erff(x * 0.70710678118654752f));
    }

    float* vb = g_v + (size_t)bh * LL + l0 + li;
    *reinterpret_cast<float4*>(vb)     = make_float4(outv[0], outv[1], outv[2], outv[3]);
    *reinterpret_cast<float4*>(vb + 4) = make_float4(outv[4], outv[5], outv[6], outv[7]);
}

// ============================================================
// Kernel 3: out[b,o,l] = sum_h W[o,h] * v[b,h,l] + bias[o]
// 128(o) x 128(l) block tile, K-chunks of 8, 8x8 microtile/thread,
// packed f32x2 FMAs on l-pairs.
// ============================================================
__global__ void __launch_bounds__(256) gemm_kernel(
    const float* __restrict__ W, const float* __restrict__ bias,
    float* __restrict__ out)
{
    int b  = blockIdx.z;
    int o0 = blockIdx.y * 128;
    int l0 = blockIdx.x * 128;
    int tid = threadIdx.x;
    int tx = tid & 15;       // l microtile
    int ty = tid >> 4;       // o microtile

    __shared__ float Ws[8][128];   // [k][o]
    __shared__ float Vs[8][128];   // [k][l]

    const float* vb = g_v + (size_t)b * HH * LL;

    unsigned long long acc[8][4];
#pragma unroll
    for (int o = 0; o < 8; o++)
#pragma unroll
        for (int p = 0; p < 4; p++) acc[o][p] = 0ull;

    int o_rel = tid >> 1;
    int s4    = (tid & 1) * 4;
    int k_rel = tid >> 5;
    int l4    = (tid & 31) * 4;

    const float* wp = W + (size_t)(o0 + o_rel) * HH + s4;
    const float* vp = vb + (size_t)k_rel * LL + l0 + l4;

    for (int kc = 0; kc < HH; kc += 8) {
        float4 wv = *reinterpret_cast<const float4*>(wp + kc);
        float4 vv = *reinterpret_cast<const float4*>(vp + (size_t)kc * LL);

        __syncthreads();
        Ws[s4 + 0][o_rel] = wv.x;
        Ws[s4 + 1][o_rel] = wv.y;
        Ws[s4 + 2][o_rel] = wv.z;
        Ws[s4 + 3][o_rel] = wv.w;
        *reinterpret_cast<float4*>(&Vs[k_rel][l4]) = vv;
        __syncthreads();

#pragma unroll
        for (int kk = 0; kk < 8; kk++) {
            float vv8[8];
            *reinterpret_cast<float4*>(vv8)     = *reinterpret_cast<const float4*>(&Vs[kk][tx * 8]);
            *reinterpret_cast<float4*>(vv8 + 4) = *reinterpret_cast<const float4*>(&Vs[kk][tx * 8 + 4]);
            const unsigned long long* vpair = reinterpret_cast<const unsigned long long*>(vv8);

            float ws8[8];
            *reinterpret_cast<float4*>(ws8)     = *reinterpret_cast<const float4*>(&Ws[kk][ty * 8]);
            *reinterpret_cast<float4*>(ws8 + 4) = *reinterpret_cast<const float4*>(&Ws[kk][ty * 8 + 4]);

#pragma unroll
            for (int o = 0; o < 8; o++) {
                unsigned long long wpair = pk2(ws8[o], ws8[o]);
                fma2(acc[o][0], wpair, vpair[0]);
                fma2(acc[o][1], wpair, vpair[1]);
                fma2(acc[o][2], wpair, vpair[2]);
                fma2(acc[o][3], wpair, vpair[3]);
            }
        }
    }

#pragma unroll
    for (int o = 0; o < 8; o++) {
        int og = o0 + ty * 8 + o;
        float bo = bias[og];
        float f[8];
#pragma unroll
        for (int p = 0; p < 4; p++) upk2(acc[o][p], f[2 * p], f[2 * p + 1]);
        float* op = out + (size_t)(b * HH + og) * LL + l0 + tx * 8;
        *reinterpret_cast<float4*>(op)     = make_float4(f[0] + bo, f[1] + bo, f[2] + bo, f[3] + bo);
        *reinterpret_cast<float4*>(op + 4) = make_float4(f[4] + bo, f[5] + bo, f[6] + bo, f[7] + bo);
    }
}

// ============================================================
extern "C" void kernel_launch(void* const* d_in, const int* in_sizes, int n_in,
                              void* d_out, int out_size)
{
    (void)in_sizes; (void)n_in; (void)out_size;
    const float* u    = (const float*)d_in[0];
    const float* k0   = (const float*)d_in[1];
    const float* k1   = (const float*)d_in[2];
    const float* k2   = (const float*)d_in[3];
    const float* k3   = (const float*)d_in[4];
    const float* D    = (const float*)d_in[5];
    const float* W    = (const float*)d_in[6];
    const float* bias = (const float*)d_in[7];
    float* out = (float*)d_out;

    build_k_kernel<<<HH, 128>>>(k0, k1, k2, k3);
    conv_gelu_kernel<<<dim3(LL / CTILE, BB * HH), 256>>>(u, D);
    gemm_kernel<<<dim3(LL / 128, HH / 128, BB), 256>>>(W, bias, out);
}

// round 6
// speedup vs baseline: 1.3666x; 1.3666x over previous
#include <cuda_runtime.h>
#include <cuda_bf16.h>
#include <cstdint>
#include <math.h>

// Problem constants
#define BB   4
#define HH   1024
#define LL   8192
#define KD   64
#define KLEN 512      // KD * 2^(NS-1)

// ---------------- static device scratch ----------------
__device__ float g_k[HH * KLEN];                         // normalized kernel [h][t]
__device__ float g_v[(size_t)BB * HH * LL];              // gelu(conv + u*D) [b][h][l]  (128 MB)
__device__ __nv_bfloat16 g_vth[(size_t)BB * LL * HH];    // v transposed hi  [b][l][h]  (64 MB)
__device__ __nv_bfloat16 g_vtl[(size_t)BB * LL * HH];    // v transposed lo  [b][l][h]  (64 MB)
__device__ __nv_bfloat16 g_Wh[HH * HH];                  // W hi [o][h]
__device__ __nv_bfloat16 g_Wl[HH * HH];                  // W lo [o][h]

// ---------------- f32x2 packed helpers ----------------
__device__ __forceinline__ unsigned long long pk2(float a, float b) {
    unsigned long long r;
    asm("mov.b64 %0, {%1, %2};" : "=l"(r) : "f"(a), "f"(b));
    return r;
}
__device__ __forceinline__ void upk2(unsigned long long v, float& a, float& b) {
    asm("mov.b64 {%0, %1}, %2;" : "=f"(a), "=f"(b) : "l"(v));
}
__device__ __forceinline__ void fma2(unsigned long long& d, unsigned long long a,
                                     unsigned long long b) {
    asm("fma.rn.f32x2 %0, %1, %2, %0;" : "+l"(d) : "l"(a), "l"(b));
}

// ---------------- PTX helpers (baseline ISA only: sm_80-class) ----------------
__device__ __forceinline__ uint32_t smem_u32(const void* p) {
    uint32_t a;
    asm("{ .reg .u64 t; cvta.to.shared.u64 t, %1; cvt.u32.u64 %0, t; }" : "=r"(a) : "l"(p));
    return a;
}
__device__ __forceinline__ void cp_async16(uint32_t sa, const void* g) {
    asm volatile("cp.async.cg.shared.global [%0], [%1], 16;" :: "r"(sa), "l"(g));
}
__device__ __forceinline__ void cp_commit() {
    asm volatile("cp.async.commit_group;" ::: "memory");
}
template<int N> __device__ __forceinline__ void cp_wait() {
    asm volatile("cp.async.wait_group %0;" :: "n"(N) : "memory");
}
__device__ __forceinline__ void ldmx4(uint32_t& r0, uint32_t& r1, uint32_t& r2, uint32_t& r3,
                                      uint32_t addr) {
    asm volatile("ldmatrix.sync.aligned.m8n8.x4.shared.b16 {%0,%1,%2,%3}, [%4];"
                 : "=r"(r0), "=r"(r1), "=r"(r2), "=r"(r3) : "r"(addr));
}
__device__ __forceinline__ void mma16816(float* c, const uint32_t* a, uint32_t b0, uint32_t b1) {
    asm volatile(
        "mma.sync.aligned.m16n8k16.row.col.f32.bf16.bf16.f32 "
        "{%0,%1,%2,%3}, {%4,%5,%6,%7}, {%8,%9}, {%0,%1,%2,%3};"
        : "+f"(c[0]), "+f"(c[1]), "+f"(c[2]), "+f"(c[3])
        : "r"(a[0]), "r"(a[1]), "r"(a[2]), "r"(a[3]), "r"(b0), "r"(b1));
}

// ============================================================
// Kernel 1: build combined, normalized conv kernel per head.
// ============================================================
__global__ void __launch_bounds__(128) build_k_kernel(
    const float* __restrict__ k0, const float* __restrict__ k1,
    const float* __restrict__ k2, const float* __restrict__ k3)
{
    int h   = blockIdx.x;
    int tid = threadIdx.x;
    const float* ks[4] = { k0 + h * KD, k1 + h * KD, k2 + h * KD, k3 + h * KD };

    float vals[4];
    float ss = 0.0f;
#pragma unroll
    for (int r = 0; r < 4; r++) {
        int t = tid + r * 128;
        float acc = 0.0f;
#pragma unroll
        for (int i = 0; i < 4; i++) {
            int len = KD << i;
            if (t < len) {
                float s = (float)(1 << i);
                float coord = (t + 0.5f) / s - 0.5f;
                coord = fminf(fmaxf(coord, 0.0f), 63.0f);
                int lo  = (int)floorf(coord);
                float w = coord - (float)lo;
                int hi  = min(lo + 1, 63);
                float val = ks[i][lo] * (1.0f - w) + ks[i][hi] * w;
                acc += val * (float)(1 << (3 - i));
            }
        }
        vals[r] = acc;
        ss += acc * acc;
    }

    __shared__ float red[128];
    red[tid] = ss;
    __syncthreads();
    for (int s = 64; s > 0; s >>= 1) {
        if (tid < s) red[tid] += red[tid + s];
        __syncthreads();
    }
    float inv = 1.0f / sqrtf(red[0]);
#pragma unroll
    for (int r = 0; r < 4; r++)
        g_k[h * KLEN + tid + r * 128] = vals[r] * inv;
}

// ============================================================
// Kernel 2: causal 512-tap conv + u*D + exact GELU -> g_v  (proven)
// ============================================================
#define CTILE 2048

__global__ void __launch_bounds__(256) conv_gelu_kernel(
    const float* __restrict__ u, const float* __restrict__ D)
{
    int bh  = blockIdx.y;
    int h   = bh & (HH - 1);
    int l0  = blockIdx.x * CTILE;
    int tid = threadIdx.x;

    __shared__ float k_s[KLEN];
    __shared__ float u_s[KLEN + CTILE];

    const float* ub = u + (size_t)bh * LL;

#pragma unroll
    for (int i = 0; i < 2; i++)
        k_s[tid + i * 256] = g_k[h * KLEN + tid + i * 256];
#pragma unroll
    for (int i = 0; i < 10; i++) {
        int idx = tid + i * 256;
        int g = l0 - KLEN + idx;
        u_s[idx] = (g >= 0) ? ub[g] : 0.0f;
    }
    __syncthreads();

    int li = tid * 8;
    const float* up = u_s + KLEN + li;

    unsigned long long acc2[4];
#pragma unroll
    for (int p = 0; p < 4; p++) acc2[p] = 0ull;

#pragma unroll 2
    for (int t = 0; t < KLEN; t += 4) {
        float4 k4 = *reinterpret_cast<const float4*>(k_s + t);
        float uv[12];
        *reinterpret_cast<float4*>(uv)     = *reinterpret_cast<const float4*>(up - t - 4);
        *reinterpret_cast<float4*>(uv + 4) = *reinterpret_cast<const float4*>(up - t);
        *reinterpret_cast<float4*>(uv + 8) = *reinterpret_cast<const float4*>(up - t + 4);
        const unsigned long long* uvl = reinterpret_cast<const unsigned long long*>(uv);

        unsigned long long kp0 = pk2(k4.x, k4.x);
        unsigned long long kp1 = pk2(k4.y, k4.y);
        unsigned long long kp2 = pk2(k4.z, k4.z);
        unsigned long long kp3 = pk2(k4.w, k4.w);
        unsigned long long po[5];
#pragma unroll
        for (int q = 0; q < 5; q++) po[q] = pk2(uv[2 * q + 1], uv[2 * q + 2]);

#pragma unroll
        for (int p = 0; p < 4; p++) {
            fma2(acc2[p], kp0, uvl[p + 2]);
            fma2(acc2[p], kp1, po[p + 1]);
            fma2(acc2[p], kp2, uvl[p + 1]);
            fma2(acc2[p], kp3, po[p]);
        }
    }

    float res[8];
#pragma unroll
    for (int p = 0; p < 4; p++) upk2(acc2[p], res[2 * p], res[2 * p + 1]);

    float d = D[h];
    float4 uc0 = *reinterpret_cast<const float4*>(up);
    float4 uc1 = *reinterpret_cast<const float4*>(up + 4);
    float uu[8] = { uc0.x, uc0.y, uc0.z, uc0.w, uc1.x, uc1.y, uc1.z, uc1.w };

    float outv[8];
#pragma unroll
    for (int r = 0; r < 8; r++) {
        float x = res[r] + uu[r] * d;
        outv[r] = 0.5f * x * (1.0f + erff(x * 0.70710678118654752f));
    }

    float* vb = g_v + (size_t)bh * LL + l0 + li;
    *reinterpret_cast<float4*>(vb)     = make_float4(outv[0], outv[1], outv[2], outv[3]);
    *reinterpret_cast<float4*>(vb + 4) = make_float4(outv[4], outv[5], outv[6], outv[7]);
}

// ============================================================
// Kernel 3: W f32 -> bf16 hi/lo (same layout [o][h])
// ============================================================
__global__ void __launch_bounds__(256) wconv_kernel(const float* __restrict__ W)
{
    int base = (blockIdx.x * 256 + threadIdx.x) * 4;
#pragma unroll
    for (int i = 0; i < 4; i++) {
        float x = W[base + i];
        __nv_bfloat16 h = __float2bfloat16(x);
        __nv_bfloat16 l = __float2bfloat16(x - __bfloat162float(h));
        g_Wh[base + i] = h;
        g_Wl[base + i] = l;
    }
}

// ============================================================
// Kernel 4: transpose + split-convert v[b][h][l] f32 -> v_t hi/lo bf16 [b][l][h]
// ============================================================
__global__ void __launch_bounds__(256) transpose_convert_kernel()
{
    int b  = blockIdx.z;
    int h0 = blockIdx.y * 64;
    int l0 = blockIdx.x * 64;
    int tid = threadIdx.x;

    __shared__ float t[64][65];

    int hi_ = tid >> 4;
    int li4 = (tid & 15) * 4;
    const float* src = g_v + ((size_t)(b * HH + h0)) * LL + l0;
#pragma unroll
    for (int r = 0; r < 4; r++) {
        int hh = hi_ + r * 16;
        float4 v4 = *reinterpret_cast<const float4*>(src + (size_t)hh * LL + li4);
        t[hh][li4]     = v4.x;
        t[hh][li4 + 1] = v4.y;
        t[hh][li4 + 2] = v4.z;
        t[hh][li4 + 3] = v4.w;
    }
    __syncthreads();

    unsigned* dh = reinterpret_cast<unsigned*>(g_vth + ((size_t)(b * LL + l0)) * HH + h0);
    unsigned* dl = reinterpret_cast<unsigned*>(g_vtl + ((size_t)(b * LL + l0)) * HH + h0);
#pragma unroll
    for (int u = 0; u < 8; u++) {
        int idx = tid + u * 256;
        int li = idx >> 5;
        int h2 = idx & 31;
        float x0 = t[2 * h2][li];
        float x1 = t[2 * h2 + 1][li];
        __nv_bfloat16 h0b = __float2bfloat16(x0);
        __nv_bfloat16 h1b = __float2bfloat16(x1);
        __nv_bfloat16 l0b = __float2bfloat16(x0 - __bfloat162float(h0b));
        __nv_bfloat16 l1b = __float2bfloat16(x1 - __bfloat162float(h1b));
        unsigned ph = (unsigned)__bfloat16_as_ushort(h0b) |
                      ((unsigned)__bfloat16_as_ushort(h1b) << 16);
        unsigned pl = (unsigned)__bfloat16_as_ushort(l0b) |
                      ((unsigned)__bfloat16_as_ushort(l1b) << 16);
        dh[(size_t)li * (HH / 2) + h2] = ph;
        dl[(size_t)li * (HH / 2) + h2] = pl;
    }
}

// ============================================================
// Kernel 5: mma.sync bf16-split GEMM (baseline ISA, tensor pipe)
// C[b,o,l] = sum_h W[o,h] v[b,h,l] + bias[o]
// CTA 128(o) x 128(l), 8 warps (2x4), warp tile 64x32.
// Effective K = 3 segments x 1024 = 3072, chunks of 32, 4-stage cp.async.
// ============================================================
#define NCH     96
#define GSTAGES 4
#define A_ROWB  80                       // padded row stride (bytes) for 64B of data
#define A_SZ    (128 * A_ROWB)           // 10240
#define STG_SZ  (2 * A_SZ)               // A + B per stage = 20480
static constexpr unsigned GEMM_SMEM = GSTAGES * STG_SZ;   // 81920

__device__ __forceinline__ void gemm_load_chunk(
    uint32_t sbase, int stage, int chunk, int o0, int b, int l0, int tid)
{
    int seg = chunk >> 5;                 // 0,1,2
    int h0  = (chunk & 31) * 32;
    const __nv_bfloat16* Aseg = (seg == 1) ? g_Wl : g_Wh;
    const __nv_bfloat16* Bseg = (seg == 2) ? g_vtl : g_vth;

    uint32_t a_s = sbase + stage * STG_SZ;
    uint32_t b_s = a_s + A_SZ;

#pragma unroll
    for (int u = 0; u < 2; u++) {
        int idx = tid + u * 256;          // 0..511
        int row = idx >> 2, c = idx & 3;
        const char* g = reinterpret_cast<const char*>(
            Aseg + (size_t)(o0 + row) * HH + h0) + c * 16;
        cp_async16(a_s + row * A_ROWB + c * 16, g);
    }
#pragma unroll
    for (int u = 0; u < 2; u++) {
        int idx = tid + u * 256;
        int row = idx >> 2, c = idx & 3;
        const char* g = reinterpret_cast<const char*>(
            Bseg + ((size_t)(b * LL + l0 + row)) * HH + h0) + c * 16;
        cp_async16(b_s + row * A_ROWB + c * 16, g);
    }
    cp_commit();
}

__global__ void __launch_bounds__(256) mma_gemm_kernel(
    const float* __restrict__ bias, float* __restrict__ out)
{
    extern __shared__ __align__(128) char smem[];
    uint32_t sbase = smem_u32(smem);
    int tid  = threadIdx.x;
    int wid  = tid >> 5, lane = tid & 31;
    int o0 = blockIdx.x * 128;            // o-tiles fastest -> B tile shared in L2
    int l0 = blockIdx.y * 128;
    int b  = blockIdx.z;

    int wm = wid & 1;                     // 0..1 -> m offset 64*wm
    int wn = wid >> 1;                    // 0..3 -> n offset 32*wn

    // ldmatrix per-lane offsets
    int a_row = ((lane >> 3) & 1) * 8 + (lane & 7);      // row within 16
    int a_cb  = (lane >> 4) * 16;                        // k-half byte offset
    int b_row = (lane >> 4) * 8 + (lane & 7);            // n within 16
    int b_cb  = ((lane >> 3) & 1) * 16;                  // k-half byte offset

    float acc[4][4][4];
#pragma unroll
    for (int mi = 0; mi < 4; mi++)
#pragma unroll
        for (int ni = 0; ni < 4; ni++)
#pragma unroll
            for (int r = 0; r < 4; r++) acc[mi][ni][r] = 0.0f;

    // prologue: stages 0..2
    gemm_load_chunk(sbase, 0, 0, o0, b, l0, tid);
    gemm_load_chunk(sbase, 1, 1, o0, b, l0, tid);
    gemm_load_chunk(sbase, 2, 2, o0, b, l0, tid);

    for (int i = 0; i < NCH; i++) {
        if (i < NCH - 3) { cp_wait<2>(); } else { cp_wait<0>(); }
        __syncthreads();

        if (i + 3 < NCH)
            gemm_load_chunk(sbase, (i + 3) & 3, i + 3, o0, b, l0, tid);

        uint32_t a_s = sbase + (i & 3) * STG_SZ;
        uint32_t b_s = a_s + A_SZ;

#pragma unroll
        for (int ks = 0; ks < 2; ks++) {
            uint32_t afrag[4][4];
#pragma unroll
            for (int mi = 0; mi < 4; mi++) {
                uint32_t addr = a_s + (wm * 64 + mi * 16 + a_row) * A_ROWB
                              + a_cb + ks * 32;
                ldmx4(afrag[mi][0], afrag[mi][1], afrag[mi][2], afrag[mi][3], addr);
            }
            uint32_t bfrag[2][4];
#pragma unroll
            for (int n2 = 0; n2 < 2; n2++) {
                uint32_t addr = b_s + (wn * 32 + n2 * 16 + b_row) * A_ROWB
                              + b_cb + ks * 32;
                ldmx4(bfrag[n2][0], bfrag[n2][1], bfrag[n2][2], bfrag[n2][3], addr);
            }
#pragma unroll
            for (int mi = 0; mi < 4; mi++)
#pragma unroll
                for (int ni = 0; ni < 4; ni++)
                    mma16816(acc[mi][ni], afrag[mi],
                             bfrag[ni >> 1][(ni & 1) * 2],
                             bfrag[ni >> 1][(ni & 1) * 2 + 1]);
        }
        __syncthreads();
    }

    // epilogue
#pragma unroll
    for (int mi = 0; mi < 4; mi++) {
        int o_a = o0 + wm * 64 + mi * 16 + (lane >> 2);
        int o_b = o_a + 8;
        float bo_a = __ldg(bias + o_a);
        float bo_b = __ldg(bias + o_b);
#pragma unroll
        for (int ni = 0; ni < 4; ni++) {
            int l = l0 + wn * 32 + ni * 8 + (lane & 3) * 2;
            float2 v0 = make_float2(acc[mi][ni][0] + bo_a, acc[mi][ni][1] + bo_a);
            float2 v1 = make_float2(acc[mi][ni][2] + bo_b, acc[mi][ni][3] + bo_b);
            *reinterpret_cast<float2*>(out + ((size_t)(b * HH + o_a)) * LL + l) = v0;
            *reinterpret_cast<float2*>(out + ((size_t)(b * HH + o_b)) * LL + l) = v1;
        }
    }
}

// ============================================================
extern "C" void kernel_launch(void* const* d_in, const int* in_sizes, int n_in,
                              void* d_out, int out_size)
{
    (void)in_sizes; (void)n_in; (void)out_size;
    const float* u    = (const float*)d_in[0];
    const float* k0   = (const float*)d_in[1];
    const float* k1   = (const float*)d_in[2];
    const float* k2   = (const float*)d_in[3];
    const float* k3   = (const float*)d_in[4];
    const float* D    = (const float*)d_in[5];
    const float* W    = (const float*)d_in[6];
    const float* bias = (const float*)d_in[7];
    float* out = (float*)d_out;

    cudaFuncSetAttribute(mma_gemm_kernel,
                         cudaFuncAttributeMaxDynamicSharedMemorySize, GEMM_SMEM);

    build_k_kernel<<<HH, 128>>>(k0, k1, k2, k3);
    conv_gelu_kernel<<<dim3(LL / CTILE, BB * HH), 256>>>(u, D);
    wconv_kernel<<<(HH * HH) / 1024, 256>>>(W);
    transpose_convert_kernel<<<dim3(LL / 64, HH / 64, BB), 256>>>();
    mma_gemm_kernel<<<dim3(HH / 128, LL / 128, BB), 256, GEMM_SMEM>>>(bias, out);
}